// round 13
// baseline (speedup 1.0000x reference)
#include <cuda_runtime.h>
#include <cuda_fp16.h>
#include <cstdint>
#include <math.h>

#define MAXN 100000
#define MAXE 1600000
#define FDIM 128
#define HID  100
#define NC   200                 // 2*HID fused output columns: [z | h]
#define BAND 64                  // fixed CSR band per node (mean deg 16)

// fp16 tensor-gemm smem geometry
#define AS_H 136                 // 272 B row ≡ 16 mod 128 -> conflict-free ldmatrix
#define BS_H 200                 // 400 B row ≡ 16 mod 128 -> conflict-free
#define CS_STRIDE 204            // f32 C stride
#define AS_BYTES (128 * AS_H * 2)          // 34,816
#define BS_BYTES (FDIM * BS_H * 2)         // 51,200
#define SMEM_BYTES (128 * CS_STRIDE * 4)   // 104,448  (C overlay dominates)

#define FIXSCALE 16777216.0f     // 2^24 fixed-point for edge-weight sums
#define FIXMASK ((1ull << 40) - 1)

// ---------------- scratch (static device memory; no runtime allocation) ----
__device__ unsigned long long g_pack[MAXN];      // (cnt<<40) | fix24(sum_w)
__device__ int   g_rank[MAXE];                   // edge rank within dst segment
__device__ __align__(16) unsigned long long g_edge[(size_t)MAXN * BAND]; // banded CSR
__device__ __align__(16) uint2 g_xh[(size_t)MAXN * 32];      // dinv*x as fp16
__device__ __align__(16) uint2 g_agg16[(size_t)MAXN * 32];   // aggx as fp16
__device__ __align__(16) __half g_Mh[FDIM * NC];             // fused weights fp16
__device__ __align__(16) float g_bias[NC];                   // fused biases

__device__ __forceinline__ float tanhfast(float x) {
    float y;
    asm("tanh.approx.f32 %0, %1;" : "=f"(y) : "f"(x));
    return y;
}
__device__ __forceinline__ void ldmatrix_x4(unsigned& r0, unsigned& r1,
                                            unsigned& r2, unsigned& r3,
                                            unsigned addr) {
    asm volatile("ldmatrix.sync.aligned.m8n8.x4.shared.b16 {%0,%1,%2,%3}, [%4];"
                 : "=r"(r0), "=r"(r1), "=r"(r2), "=r"(r3) : "r"(addr));
}
__device__ __forceinline__ void ldmatrix_x2_trans(unsigned& r0, unsigned& r1,
                                                  unsigned addr) {
    asm volatile("ldmatrix.sync.aligned.m8n8.x2.trans.shared.b16 {%0,%1}, [%2];"
                 : "=r"(r0), "=r"(r1) : "r"(addr));
}
__device__ __forceinline__ void mma_f16(float* c, const unsigned* a,
                                        unsigned b0, unsigned b1) {
    asm volatile(
        "mma.sync.aligned.m16n8k16.row.col.f32.f16.f16.f32 "
        "{%0,%1,%2,%3},{%4,%5,%6,%7},{%8,%9},{%0,%1,%2,%3};"
        : "+f"(c[0]), "+f"(c[1]), "+f"(c[2]), "+f"(c[3])
        : "r"(a[0]), "r"(a[1]), "r"(a[2]), "r"(a[3]), "r"(b0), "r"(b1));
}
__device__ __forceinline__ float4 h4_to_f4(unsigned lo, unsigned hi) {
    float2 fa = __half22float2(*(__half2*)&lo);
    float2 fb = __half22float2(*(__half2*)&hi);
    return make_float4(fa.x, fa.y, fb.x, fb.y);
}
__device__ __forceinline__ float pack_dinv(unsigned long long p) {
    float deg = 1.0f + (float)(p & FIXMASK) * (1.0f / FIXSCALE);
    return rsqrtf(deg);
}

// ---------------- fused weights+bias + scratch zeroing (one launch) ---------
__global__ void __launch_bounds__(128) k_fuse(
        const float* __restrict__ Wcz, const float* __restrict__ Wch,
        const float* __restrict__ bcz, const float* __restrict__ bch,
        const float* __restrict__ Wlz, const float* __restrict__ Wlh,
        const float* __restrict__ blz, const float* __restrict__ blh, int n) {
    if (blockIdx.x >= NC) {
        int i = (blockIdx.x - NC) * 128 + threadIdx.x;
        if (i < n) g_pack[i] = 0ull;
        return;
    }
    __shared__ float wl[HID];
    __shared__ float red[128];
    int j = blockIdx.x;                 // 0..199
    int t = threadIdx.x;                // 0..127
    int jj = (j < HID) ? j : j - HID;
    const float* A  = (j < HID) ? Wcz : Wch;
    const float* bc = (j < HID) ? bcz : bch;
    const float* Wl = (j < HID) ? Wlz : Wlh;
    const float* bl = (j < HID) ? blz : blh;

    float p = 0.0f;
    if (t < HID) {
        float v = Wl[t * HID + jj];
        wl[t] = v;
        p = bc[t] * v;
    }
    red[t] = p;
    __syncthreads();

    const float* Ar = A + t * HID;
    float s = 0.0f;
    #pragma unroll 4
    for (int k = 0; k < HID; k++)
        s = fmaf(Ar[k], wl[k], s);
    g_Mh[t * NC + j] = __float2half_rn(s);

    #pragma unroll
    for (int off = 64; off > 0; off >>= 1) {
        if (t < off) red[t] += red[t + off];
        __syncthreads();
    }
    if (t == 0) g_bias[j] = bl[jj] + red[0];
}

// ---------------- per-edge: packed atomic; prior count = edge rank (free) ---
__global__ void k_deg_acc(const int* __restrict__ ei,
                          const float* __restrict__ ew, int e) {
    int i = blockIdx.x * blockDim.x + threadIdx.x;
    if (i < e) {
        int d = ei[(size_t)e + i];
        unsigned long long fix =
            (unsigned long long)__float2uint_rn(ew[i] * FIXSCALE);
        unsigned long long prior = atomicAdd(&g_pack[d], (1ull << 40) | fix);
        g_rank[i] = (int)(prior >> 40);
    }
}

// ---------------- merged: banded fill (no scan needed) + prep xs=dinv*x -----
// blocks [0, fb): fill edges at dst*BAND+rank; blocks [fb, ...): prep features
__global__ void k_fillprep(const int* __restrict__ ei,
                           const float* __restrict__ ew,
                           const float* __restrict__ x,
                           int e, int n, int fb) {
    if (blockIdx.x < fb) {
        int i = blockIdx.x * 256 + threadIdx.x;
        if (i >= e) return;
        int s = ei[i];
        int d = ei[(size_t)e + i];
        int r = g_rank[i];
        if (r < BAND)
            g_edge[((size_t)d << 6) + r] =
                (unsigned long long)(unsigned)s |
                ((unsigned long long)__float_as_uint(ew[i]) << 32);
    } else {
        int i = (blockIdx.x - fb) * 256 + threadIdx.x;
        if (i >= n * 32) return;
        float dd = pack_dinv(g_pack[i >> 5]);
        float4 v = ((const float4*)x)[i];
        uint2 u;
        *(__half2*)&u.x = __floats2half2_rn(v.x * dd, v.y * dd);
        *(__half2*)&u.y = __floats2half2_rn(v.z * dd, v.w * dd);
        g_xh[i] = u;
    }
}

// ---------------- gather: 2 nodes/warp, banded CSR, fp32 accum --------------
// agg[d] = dd * ( xs[d] + sum_e w_e * xs[src_e] ),  xs = dinv*x
__global__ void k_gather(int n) {
    int w = (blockIdx.x * blockDim.x + threadIdx.x) >> 5;
    int lane = threadIdx.x & 31;
    int sub = lane >> 4, sl = lane & 15;
    int node = w * 2 + sub;
    if (node >= n) return;
    unsigned long long p = g_pack[node];
    int cnt = (int)(p >> 40);
    if (cnt > BAND) cnt = BAND;
    float dd = pack_dinv(p);
    int beg = node << 6;

    const uint4* xh4 = (const uint4*)g_xh;        // 16 uint4 per node row
    uint4 u = xh4[(size_t)node * 16 + sl];
    float4 a0 = h4_to_f4(u.x, u.y);               // xs[d], NO dd here
    float4 a1 = h4_to_f4(u.z, u.w);

    int j = beg, end = beg + cnt;
    int m4 = beg + (cnt & ~3);
    for (; j < m4; j += 4) {
        unsigned long long m0 = g_edge[j];
        unsigned long long m1 = g_edge[j + 1];
        unsigned long long m2 = g_edge[j + 2];
        unsigned long long m3 = g_edge[j + 3];
        uint4 v0 = xh4[(size_t)(unsigned)m0 * 16 + sl];
        uint4 v1 = xh4[(size_t)(unsigned)m1 * 16 + sl];
        uint4 v2 = xh4[(size_t)(unsigned)m2 * 16 + sl];
        uint4 v3 = xh4[(size_t)(unsigned)m3 * 16 + sl];
        float w0 = __uint_as_float((unsigned)(m0 >> 32));
        float w1 = __uint_as_float((unsigned)(m1 >> 32));
        float w2 = __uint_as_float((unsigned)(m2 >> 32));
        float w3 = __uint_as_float((unsigned)(m3 >> 32));
        float4 f;
        f = h4_to_f4(v0.x, v0.y);
        a0.x = fmaf(f.x, w0, a0.x); a0.y = fmaf(f.y, w0, a0.y);
        a0.z = fmaf(f.z, w0, a0.z); a0.w = fmaf(f.w, w0, a0.w);
        f = h4_to_f4(v0.z, v0.w);
        a1.x = fmaf(f.x, w0, a1.x); a1.y = fmaf(f.y, w0, a1.y);
        a1.z = fmaf(f.z, w0, a1.z); a1.w = fmaf(f.w, w0, a1.w);
        f = h4_to_f4(v1.x, v1.y);
        a0.x = fmaf(f.x, w1, a0.x); a0.y = fmaf(f.y, w1, a0.y);
        a0.z = fmaf(f.z, w1, a0.z); a0.w = fmaf(f.w, w1, a0.w);
        f = h4_to_f4(v1.z, v1.w);
        a1.x = fmaf(f.x, w1, a1.x); a1.y = fmaf(f.y, w1, a1.y);
        a1.z = fmaf(f.z, w1, a1.z); a1.w = fmaf(f.w, w1, a1.w);
        f = h4_to_f4(v2.x, v2.y);
        a0.x = fmaf(f.x, w2, a0.x); a0.y = fmaf(f.y, w2, a0.y);
        a0.z = fmaf(f.z, w2, a0.z); a0.w = fmaf(f.w, w2, a0.w);
        f = h4_to_f4(v2.z, v2.w);
        a1.x = fmaf(f.x, w2, a1.x); a1.y = fmaf(f.y, w2, a1.y);
        a1.z = fmaf(f.z, w2, a1.z); a1.w = fmaf(f.w, w2, a1.w);
        f = h4_to_f4(v3.x, v3.y);
        a0.x = fmaf(f.x, w3, a0.x); a0.y = fmaf(f.y, w3, a0.y);
        a0.z = fmaf(f.z, w3, a0.z); a0.w = fmaf(f.w, w3, a0.w);
        f = h4_to_f4(v3.z, v3.w);
        a1.x = fmaf(f.x, w3, a1.x); a1.y = fmaf(f.y, w3, a1.y);
        a1.z = fmaf(f.z, w3, a1.z); a1.w = fmaf(f.w, w3, a1.w);
    }
    for (; j < end; j++) {
        unsigned long long m = g_edge[j];
        float wq = __uint_as_float((unsigned)(m >> 32));
        uint4 v = xh4[(size_t)(unsigned)m * 16 + sl];
        float4 f = h4_to_f4(v.x, v.y);
        a0.x = fmaf(f.x, wq, a0.x); a0.y = fmaf(f.y, wq, a0.y);
        a0.z = fmaf(f.z, wq, a0.z); a0.w = fmaf(f.w, wq, a0.w);
        f = h4_to_f4(v.z, v.w);
        a1.x = fmaf(f.x, wq, a1.x); a1.y = fmaf(f.y, wq, a1.y);
        a1.z = fmaf(f.z, wq, a1.z); a1.w = fmaf(f.w, wq, a1.w);
    }
    uint4 o;
    *(__half2*)&o.x = __floats2half2_rn(a0.x * dd, a0.y * dd);
    *(__half2*)&o.y = __floats2half2_rn(a0.z * dd, a0.w * dd);
    *(__half2*)&o.z = __floats2half2_rn(a1.x * dd, a1.y * dd);
    *(__half2*)&o.w = __floats2half2_rn(a1.z * dd, a1.w * dd);
    ((uint4*)g_agg16)[(size_t)node * 16 + sl] = o;
}

// ---------------- fp16 tensor-core GEMM + fused TGCN epilogue ---------------
__global__ void __launch_bounds__(256, 1)
k_tgemm(const float* __restrict__ Wout, const float* __restrict__ bout,
        float* __restrict__ out, int n) {
    extern __shared__ __align__(16) char smem[];
    __half* As = (__half*)smem;                        // [128][AS_H]
    __half* Bs = (__half*)(smem + AS_BYTES);           // [FDIM][BS_H]

    __shared__ float sbias[NC];
    __shared__ float swout[HID];
    __shared__ float sbout;

    int tid = threadIdx.x;
    int n0 = blockIdx.x * 128;

    if (tid < NC)  sbias[tid] = g_bias[tid];
    if (tid < HID) swout[tid] = Wout[tid];
    if (tid == 0)  sbout = bout[0];

    for (int idx = tid; idx < 128 * 32; idx += 256) {
        int r = idx >> 5, c4 = idx & 31;
        int nn = n0 + r;
        uint2 u = (nn < n) ? g_agg16[(size_t)nn * 32 + c4] : make_uint2(0u, 0u);
        *(uint2*)&As[r * AS_H + c4 * 4] = u;
    }
    for (int idx = tid; idx < FDIM * 50; idx += 256) {
        int k = idx / 50, c = idx % 50;
        *(uint2*)&Bs[k * BS_H + c * 4] = ((const uint2*)g_Mh)[k * 50 + c];
    }
    __syncthreads();

    int lane = tid & 31, w = tid >> 5;
    int mw = w & 3, nw = w >> 2;
    int rbase = mw * 32;
    int nbase = nw * 96;
    int lr = lane >> 2, lc = lane & 3;

    unsigned as_base = (unsigned)__cvta_generic_to_shared(As);
    unsigned bs_base = (unsigned)__cvta_generic_to_shared(Bs);

    int a_idx = lane & 7, a_grp = lane >> 3;
    int b_row_lane = lane & 15;

    float c[2][13][4];
    #pragma unroll
    for (int ms = 0; ms < 2; ms++)
        #pragma unroll
        for (int t = 0; t < 13; t++)
            #pragma unroll
            for (int u = 0; u < 4; u++) c[ms][t][u] = 0.0f;

    #pragma unroll
    for (int ks = 0; ks < 8; ks++) {
        int k0 = ks * 16;
        unsigned a[2][4];
        #pragma unroll
        for (int ms = 0; ms < 2; ms++) {
            int row = rbase + ms * 16 + (a_grp & 1) * 8 + a_idx;
            int col = k0 + (a_grp >> 1) * 8;
            unsigned addr = as_base + (row * AS_H + col) * 2;
            ldmatrix_x4(a[ms][0], a[ms][1], a[ms][2], a[ms][3], addr);
        }
        #pragma unroll
        for (int t = 0; t < 13; t++) {
            int ncol = nbase + t * 8;
            unsigned baddr = bs_base + ((k0 + b_row_lane) * BS_H + ncol) * 2;
            unsigned b0, b1;
            ldmatrix_x2_trans(b0, b1, baddr);
            mma_f16(c[0][t], a[0], b0, b1);
            mma_f16(c[1][t], a[1], b0, b1);
        }
    }

    __syncthreads();
    float* Cs = (float*)smem;
    #pragma unroll
    for (int ms = 0; ms < 2; ms++) {
        #pragma unroll
        for (int t = 0; t < 13; t++) {
            int rr = rbase + ms * 16 + lr;
            int cc = nbase + t * 8 + lc * 2;
            *(float2*)&Cs[rr * CS_STRIDE + cc] =
                make_float2(c[ms][t][0], c[ms][t][1]);
            *(float2*)&Cs[(rr + 8) * CS_STRIDE + cc] =
                make_float2(c[ms][t][2], c[ms][t][3]);
        }
    }
    __syncthreads();

    int r = tid >> 1, half = tid & 1;
    int nn = n0 + r;
    const float* Cr = &Cs[r * CS_STRIDE];
    float sum = 0.0f;
    #pragma unroll 2
    for (int jj = 0; jj < 50; jj++) {
        int j = half * 50 + jj;
        float zr = Cr[j] + sbias[j];
        float hr = Cr[HID + j] + sbias[HID + j];
        float omz = 0.5f * (1.0f - tanhfast(0.5f * zr));   // 1 - sigmoid(zr)
        float v = fmaxf(omz * tanhfast(hr), 0.0f);
        sum = fmaf(v, swout[j], sum);
    }
    sum += __shfl_down_sync(0xffffffffu, sum, 1);
    if (half == 0 && nn < n) out[nn] = sum + sbout;
}

// ---------------- launch ----------------------------------------------------
extern "C" void kernel_launch(void* const* d_in, const int* in_sizes, int n_in,
                              void* d_out, int out_size) {
    const float* x    = (const float*)d_in[0];
    const int*   ei   = (const int*)d_in[1];     // int32 (JAX canonicalizes)
    const float* ew   = (const float*)d_in[2];
    const float* Wcz  = (const float*)d_in[3];
    const float* bcz  = (const float*)d_in[4];
    const float* Wch  = (const float*)d_in[7];
    const float* bch  = (const float*)d_in[8];
    const float* Wlz  = (const float*)d_in[9];
    const float* blz  = (const float*)d_in[10];
    const float* Wlh  = (const float*)d_in[13];
    const float* blh  = (const float*)d_in[14];
    const float* Wout = (const float*)d_in[15];
    const float* bout = (const float*)d_in[16];
    float*       out  = (float*)d_out;

    int n = in_sizes[0] / FDIM;    // 100000
    int e = in_sizes[2];           // 1600000

    static bool attr_set = false;
    if (!attr_set) {
        cudaFuncSetAttribute(k_tgemm,
                             cudaFuncAttributeMaxDynamicSharedMemorySize,
                             SMEM_BYTES);
        attr_set = true;
    }

    k_fuse<<<NC + (n + 127) / 128, 128>>>(Wcz, Wch, bcz, bch,
                                          Wlz, Wlh, blz, blh, n);
    k_deg_acc<<<(e + 255) / 256, 256>>>(ei, ew, e);
    int fb = (e + 255) / 256;
    int pb = (n * 32 + 255) / 256;
    k_fillprep<<<fb + pb, 256>>>(ei, ew, x, e, n, fb);
    int gwarps = (n + 1) / 2;
    k_gather<<<(gwarps * 32 + 255) / 256, 256>>>(n);
    k_tgemm<<<(n + 127) / 128, 256, SMEM_BYTES>>>(Wout, bout, out, n);
}

// round 14
// speedup vs baseline: 1.0645x; 1.0645x over previous
#include <cuda_runtime.h>
#include <cuda_fp16.h>
#include <cstdint>
#include <math.h>

#define MAXN 100000
#define MAXE 1600000
#define FDIM 128
#define HID  100
#define NC   200                 // 2*HID fused output columns: [z | h]
#define SCAN_BLK 1024

// fp16 tensor-gemm smem geometry
#define AS_H 136                 // 272 B row ≡ 16 mod 128 -> conflict-free ldmatrix
#define BS_H 200                 // 400 B row ≡ 16 mod 128 -> conflict-free
#define CS_STRIDE 204            // f32 C stride
#define AS_BYTES (128 * AS_H * 2)          // 34,816
#define BS_BYTES (FDIM * BS_H * 2)         // 51,200
#define SMEM_BYTES (128 * CS_STRIDE * 4)   // 104,448  (C overlay dominates)

#define FIXSCALE 16777216.0f     // 2^24 fixed-point for edge-weight sums
#define FIXMASK ((1ull << 40) - 1)

// ---------------- scratch (static device memory; no runtime allocation) ----
__device__ unsigned long long g_pack[MAXN];      // (cnt<<40) | fix24(sum_w)
__device__ __align__(16) float g_dinv[MAXN];
__device__ unsigned long long g_offcnt[MAXN];    // off | (cnt<<32)
__device__ int   g_rank[MAXE];                   // edge rank within dst segment
__device__ int   g_total;                        // global scan cursor
__device__ __align__(16) unsigned long long g_edge[MAXE];    // packed (src, w)
__device__ __align__(16) uint2 g_xh[(size_t)MAXN * 32];      // dinv*x as fp16
__device__ __align__(16) uint2 g_agg16[(size_t)MAXN * 32];   // aggx as fp16
__device__ __align__(16) __half g_Mh[FDIM * NC];             // fused weights fp16
__device__ __align__(16) float g_bias[NC];                   // fused biases

__device__ __forceinline__ float tanhfast(float x) {
    float y;
    asm("tanh.approx.f32 %0, %1;" : "=f"(y) : "f"(x));
    return y;
}
__device__ __forceinline__ void ldmatrix_x4(unsigned& r0, unsigned& r1,
                                            unsigned& r2, unsigned& r3,
                                            unsigned addr) {
    asm volatile("ldmatrix.sync.aligned.m8n8.x4.shared.b16 {%0,%1,%2,%3}, [%4];"
                 : "=r"(r0), "=r"(r1), "=r"(r2), "=r"(r3) : "r"(addr));
}
__device__ __forceinline__ void ldmatrix_x2_trans(unsigned& r0, unsigned& r1,
                                                  unsigned addr) {
    asm volatile("ldmatrix.sync.aligned.m8n8.x2.trans.shared.b16 {%0,%1}, [%2];"
                 : "=r"(r0), "=r"(r1) : "r"(addr));
}
__device__ __forceinline__ void mma_f16(float* c, const unsigned* a,
                                        unsigned b0, unsigned b1) {
    asm volatile(
        "mma.sync.aligned.m16n8k16.row.col.f32.f16.f16.f32 "
        "{%0,%1,%2,%3},{%4,%5,%6,%7},{%8,%9},{%0,%1,%2,%3};"
        : "+f"(c[0]), "+f"(c[1]), "+f"(c[2]), "+f"(c[3])
        : "r"(a[0]), "r"(a[1]), "r"(a[2]), "r"(a[3]), "r"(b0), "r"(b1));
}
__device__ __forceinline__ float4 h4_to_f4(unsigned lo, unsigned hi) {
    float2 fa = __half22float2(*(__half2*)&lo);
    float2 fb = __half22float2(*(__half2*)&hi);
    return make_float4(fa.x, fa.y, fb.x, fb.y);
}

// ---------------- fused weights+bias + scratch zeroing (one launch) ---------
__global__ void __launch_bounds__(128) k_fuse(
        const float* __restrict__ Wcz, const float* __restrict__ Wch,
        const float* __restrict__ bcz, const float* __restrict__ bch,
        const float* __restrict__ Wlz, const float* __restrict__ Wlh,
        const float* __restrict__ blz, const float* __restrict__ blh, int n) {
    if (blockIdx.x >= NC) {
        int i = (blockIdx.x - NC) * 128 + threadIdx.x;
        if (i < n) g_pack[i] = 0ull;
        if (blockIdx.x == NC && threadIdx.x == 0) g_total = 0;
        return;
    }
    __shared__ float wl[HID];
    __shared__ float red[128];
    int j = blockIdx.x;                 // 0..199
    int t = threadIdx.x;                // 0..127
    int jj = (j < HID) ? j : j - HID;
    const float* A  = (j < HID) ? Wcz : Wch;
    const float* bc = (j < HID) ? bcz : bch;
    const float* Wl = (j < HID) ? Wlz : Wlh;
    const float* bl = (j < HID) ? blz : blh;

    float p = 0.0f;
    if (t < HID) {
        float v = Wl[t * HID + jj];
        wl[t] = v;
        p = bc[t] * v;
    }
    red[t] = p;
    __syncthreads();

    const float* Ar = A + t * HID;
    float s = 0.0f;
    #pragma unroll 4
    for (int k = 0; k < HID; k++)
        s = fmaf(Ar[k], wl[k], s);
    g_Mh[t * NC + j] = __float2half_rn(s);

    #pragma unroll
    for (int off = 64; off > 0; off >>= 1) {
        if (t < off) red[t] += red[t + off];
        __syncthreads();
    }
    if (t == 0) g_bias[j] = bl[jj] + red[0];
}

// ---------------- per-edge: packed atomic; prior count = edge rank (free) ---
__global__ void k_deg_acc(const int* __restrict__ ei,
                          const float* __restrict__ ew, int e) {
    int i = blockIdx.x * blockDim.x + threadIdx.x;
    if (i < e) {
        int d = ei[(size_t)e + i];
        unsigned long long fix =
            (unsigned long long)__float2uint_rn(ew[i] * FIXSCALE);
        unsigned long long prior = atomicAdd(&g_pack[d], (1ull << 40) | fix);
        g_rank[i] = (int)(prior >> 40);
    }
}

// ---------------- ONE-kernel scan: decode + local scan + atomic block base --
__global__ void k_scan(int n) {
    __shared__ int s[SCAN_BLK];
    __shared__ int base;
    int t = threadIdx.x;
    int idx = blockIdx.x * SCAN_BLK + t;
    int val = 0;
    if (idx < n) {
        unsigned long long p = g_pack[idx];
        val = (int)(p >> 40);
        float deg = 1.0f + (float)(p & FIXMASK) * (1.0f / FIXSCALE);
        g_dinv[idx] = rsqrtf(deg);
    }
    s[t] = val;
    __syncthreads();
    #pragma unroll
    for (int off = 1; off < SCAN_BLK; off <<= 1) {
        int v = (t >= off) ? s[t - off] : 0;
        __syncthreads();
        s[t] += v;
        __syncthreads();
    }
    if (t == SCAN_BLK - 1) base = atomicAdd(&g_total, s[t]);
    __syncthreads();
    if (idx < n) {
        int off = base + s[t] - val;        // exclusive
        g_offcnt[idx] = (unsigned long long)(unsigned)off |
                        ((unsigned long long)(unsigned)val << 32);
    }
}

// ---------------- merged: fill CSR (no atomics) + prep xs=dinv*x ------------
__global__ void k_fillprep(const int* __restrict__ ei,
                           const float* __restrict__ ew,
                           const float* __restrict__ x,
                           int e, int n, int fb) {
    if (blockIdx.x < fb) {
        int i = blockIdx.x * 256 + threadIdx.x;
        if (i >= e) return;
        int s = ei[i];
        int d = ei[(size_t)e + i];
        int pos = (int)(unsigned)g_offcnt[d] + g_rank[i];
        g_edge[pos] = (unsigned long long)(unsigned)s |
                      ((unsigned long long)__float_as_uint(ew[i]) << 32);
    } else {
        int i = (blockIdx.x - fb) * 256 + threadIdx.x;
        if (i >= n * 32) return;
        float dd = g_dinv[i >> 5];
        float4 v = ((const float4*)x)[i];
        uint2 u;
        *(__half2*)&u.x = __floats2half2_rn(v.x * dd, v.y * dd);
        *(__half2*)&u.y = __floats2half2_rn(v.z * dd, v.w * dd);
        g_xh[i] = u;
    }
}

// ---------------- gather v3: 2 nodes/warp, HFMA2 group-4 accumulation -------
// agg[d] = dd * ( xs[d] + sum_e w_e * xs[src_e] ),  xs = dinv*x
// fp16 partial sums over groups of 4 edges, flushed to fp32 accumulators.
__global__ void k_gather(int n) {
    int w = (blockIdx.x * blockDim.x + threadIdx.x) >> 5;
    int lane = threadIdx.x & 31;
    int sub = lane >> 4, sl = lane & 15;
    int node = w * 2 + sub;
    if (node >= n) return;
    unsigned long long oc = g_offcnt[node];
    int beg = (int)(unsigned)oc;
    int cnt = (int)(oc >> 32);
    float dd = g_dinv[node];

    const uint4* xh4 = (const uint4*)g_xh;        // 16 uint4 per node row
    uint4 u = xh4[(size_t)node * 16 + sl];
    float4 a0 = h4_to_f4(u.x, u.y);               // xs[d]
    float4 a1 = h4_to_f4(u.z, u.w);

    int j = beg, end = beg + cnt;
    int m4 = beg + (cnt & ~3);
    const __half2 z2 = __floats2half2_rn(0.0f, 0.0f);
    for (; j < m4; j += 4) {
        __half2 h0 = z2, h1 = z2, h2 = z2, h3 = z2;
        #pragma unroll
        for (int q = 0; q < 4; q++) {
            unsigned long long m = g_edge[j + q];
            uint4 v = xh4[(size_t)(unsigned)m * 16 + sl];
            __half2 wh =
                __float2half2_rn(__uint_as_float((unsigned)(m >> 32)));
            h0 = __hfma2(*(__half2*)&v.x, wh, h0);
            h1 = __hfma2(*(__half2*)&v.y, wh, h1);
            h2 = __hfma2(*(__half2*)&v.z, wh, h2);
            h3 = __hfma2(*(__half2*)&v.w, wh, h3);
        }
        float2 f;
        f = __half22float2(h0); a0.x += f.x; a0.y += f.y;
        f = __half22float2(h1); a0.z += f.x; a0.w += f.y;
        f = __half22float2(h2); a1.x += f.x; a1.y += f.y;
        f = __half22float2(h3); a1.z += f.x; a1.w += f.y;
    }
    for (; j < end; j++) {
        unsigned long long m = g_edge[j];
        float wq = __uint_as_float((unsigned)(m >> 32));
        uint4 v = xh4[(size_t)(unsigned)m * 16 + sl];
        float4 f = h4_to_f4(v.x, v.y);
        a0.x = fmaf(f.x, wq, a0.x); a0.y = fmaf(f.y, wq, a0.y);
        a0.z = fmaf(f.z, wq, a0.z); a0.w = fmaf(f.w, wq, a0.w);
        f = h4_to_f4(v.z, v.w);
        a1.x = fmaf(f.x, wq, a1.x); a1.y = fmaf(f.y, wq, a1.y);
        a1.z = fmaf(f.z, wq, a1.z); a1.w = fmaf(f.w, wq, a1.w);
    }
    uint4 o;
    *(__half2*)&o.x = __floats2half2_rn(a0.x * dd, a0.y * dd);
    *(__half2*)&o.y = __floats2half2_rn(a0.z * dd, a0.w * dd);
    *(__half2*)&o.z = __floats2half2_rn(a1.x * dd, a1.y * dd);
    *(__half2*)&o.w = __floats2half2_rn(a1.z * dd, a1.w * dd);
    ((uint4*)g_agg16)[(size_t)node * 16 + sl] = o;
}

// ---------------- fp16 tensor-core GEMM + fused TGCN epilogue ---------------
__global__ void __launch_bounds__(256, 1)
k_tgemm(const float* __restrict__ Wout, const float* __restrict__ bout,
        float* __restrict__ out, int n) {
    extern __shared__ __align__(16) char smem[];
    __half* As = (__half*)smem;                        // [128][AS_H]
    __half* Bs = (__half*)(smem + AS_BYTES);           // [FDIM][BS_H]

    __shared__ float sbias[NC];
    __shared__ float swout[HID];
    __shared__ float sbout;

    int tid = threadIdx.x;
    int n0 = blockIdx.x * 128;

    if (tid < NC)  sbias[tid] = g_bias[tid];
    if (tid < HID) swout[tid] = Wout[tid];
    if (tid == 0)  sbout = bout[0];

    for (int idx = tid; idx < 128 * 32; idx += 256) {
        int r = idx >> 5, c4 = idx & 31;
        int nn = n0 + r;
        uint2 u = (nn < n) ? g_agg16[(size_t)nn * 32 + c4] : make_uint2(0u, 0u);
        *(uint2*)&As[r * AS_H + c4 * 4] = u;
    }
    for (int idx = tid; idx < FDIM * 50; idx += 256) {
        int k = idx / 50, c = idx % 50;
        *(uint2*)&Bs[k * BS_H + c * 4] = ((const uint2*)g_Mh)[k * 50 + c];
    }
    __syncthreads();

    int lane = tid & 31, w = tid >> 5;
    int mw = w & 3, nw = w >> 2;
    int rbase = mw * 32;
    int nbase = nw * 96;
    int lr = lane >> 2, lc = lane & 3;

    unsigned as_base = (unsigned)__cvta_generic_to_shared(As);
    unsigned bs_base = (unsigned)__cvta_generic_to_shared(Bs);

    int a_idx = lane & 7, a_grp = lane >> 3;
    int b_row_lane = lane & 15;

    float c[2][13][4];
    #pragma unroll
    for (int ms = 0; ms < 2; ms++)
        #pragma unroll
        for (int t = 0; t < 13; t++)
            #pragma unroll
            for (int u = 0; u < 4; u++) c[ms][t][u] = 0.0f;

    #pragma unroll
    for (int ks = 0; ks < 8; ks++) {
        int k0 = ks * 16;
        unsigned a[2][4];
        #pragma unroll
        for (int ms = 0; ms < 2; ms++) {
            int row = rbase + ms * 16 + (a_grp & 1) * 8 + a_idx;
            int col = k0 + (a_grp >> 1) * 8;
            unsigned addr = as_base + (row * AS_H + col) * 2;
            ldmatrix_x4(a[ms][0], a[ms][1], a[ms][2], a[ms][3], addr);
        }
        #pragma unroll
        for (int t = 0; t < 13; t++) {
            int ncol = nbase + t * 8;
            unsigned baddr = bs_base + ((k0 + b_row_lane) * BS_H + ncol) * 2;
            unsigned b0, b1;
            ldmatrix_x2_trans(b0, b1, baddr);
            mma_f16(c[0][t], a[0], b0, b1);
            mma_f16(c[1][t], a[1], b0, b1);
        }
    }

    __syncthreads();
    float* Cs = (float*)smem;
    #pragma unroll
    for (int ms = 0; ms < 2; ms++) {
        #pragma unroll
        for (int t = 0; t < 13; t++) {
            int rr = rbase + ms * 16 + lr;
            int cc = nbase + t * 8 + lc * 2;
            *(float2*)&Cs[rr * CS_STRIDE + cc] =
                make_float2(c[ms][t][0], c[ms][t][1]);
            *(float2*)&Cs[(rr + 8) * CS_STRIDE + cc] =
                make_float2(c[ms][t][2], c[ms][t][3]);
        }
    }
    __syncthreads();

    int r = tid >> 1, half = tid & 1;
    int nn = n0 + r;
    const float* Cr = &Cs[r * CS_STRIDE];
    float sum = 0.0f;
    #pragma unroll 2
    for (int jj = 0; jj < 50; jj++) {
        int j = half * 50 + jj;
        float zr = Cr[j] + sbias[j];
        float hr = Cr[HID + j] + sbias[HID + j];
        float omz = 0.5f * (1.0f - tanhfast(0.5f * zr));   // 1 - sigmoid(zr)
        float v = fmaxf(omz * tanhfast(hr), 0.0f);
        sum = fmaf(v, swout[j], sum);
    }
    sum += __shfl_down_sync(0xffffffffu, sum, 1);
    if (half == 0 && nn < n) out[nn] = sum + sbout;
}

// ---------------- launch ----------------------------------------------------
extern "C" void kernel_launch(void* const* d_in, const int* in_sizes, int n_in,
                              void* d_out, int out_size) {
    const float* x    = (const float*)d_in[0];
    const int*   ei   = (const int*)d_in[1];     // int32 (JAX canonicalizes)
    const float* ew   = (const float*)d_in[2];
    const float* Wcz  = (const float*)d_in[3];
    const float* bcz  = (const float*)d_in[4];
    const float* Wch  = (const float*)d_in[7];
    const float* bch  = (const float*)d_in[8];
    const float* Wlz  = (const float*)d_in[9];
    const float* blz  = (const float*)d_in[10];
    const float* Wlh  = (const float*)d_in[13];
    const float* blh  = (const float*)d_in[14];
    const float* Wout = (const float*)d_in[15];
    const float* bout = (const float*)d_in[16];
    float*       out  = (float*)d_out;

    int n = in_sizes[0] / FDIM;    // 100000
    int e = in_sizes[2];           // 1600000
    int nb = (n + SCAN_BLK - 1) / SCAN_BLK;

    static bool attr_set = false;
    if (!attr_set) {
        cudaFuncSetAttribute(k_tgemm,
                             cudaFuncAttributeMaxDynamicSharedMemorySize,
                             SMEM_BYTES);
        attr_set = true;
    }

    k_fuse<<<NC + (n + 127) / 128, 128>>>(Wcz, Wch, bcz, bch,
                                          Wlz, Wlh, blz, blh, n);
    k_deg_acc<<<(e + 255) / 256, 256>>>(ei, ew, e);
    k_scan<<<nb, SCAN_BLK>>>(n);
    int fb = (e + 255) / 256;
    int pb = (n * 32 + 255) / 256;
    k_fillprep<<<fb + pb, 256>>>(ei, ew, x, e, n, fb);
    int gwarps = (n + 1) / 2;
    k_gather<<<(gwarps * 32 + 255) / 256, 256>>>(n);
    k_tgemm<<<(n + 127) / 128, 256, SMEM_BYTES>>>(Wout, bout, out, n);
}

// round 15
// speedup vs baseline: 1.0774x; 1.0121x over previous
#include <cuda_runtime.h>
#include <cuda_fp16.h>
#include <cstdint>
#include <math.h>

#define MAXN 100000
#define MAXE 1600000
#define FDIM 128
#define HID  100
#define NC   200                 // 2*HID fused output columns: [z | h]
#define SCAN_BLK 1024

// fp16 tensor-gemm smem geometry
#define AS_H 136                 // 272 B row ≡ 16 mod 128 -> conflict-free ldmatrix
#define BS_H 200                 // 400 B row ≡ 16 mod 128 -> conflict-free
#define CS_STRIDE 204            // f32 C stride
#define AS_BYTES (128 * AS_H * 2)          // 34,816
#define BS_BYTES (FDIM * BS_H * 2)         // 51,200
#define SMEM_BYTES (128 * CS_STRIDE * 4)   // 104,448  (C overlay dominates)

#define FIXSCALE 16777216.0f     // 2^24 fixed-point for edge-weight degree sums
#define FIXMASK ((1ull << 40) - 1)
#define WQ 32767.0f              // 15-bit edge-weight quantization
#define SRCMASK 0x1FFFFu         // 17 bits for src (N = 1e5 < 2^17)

// ---------------- scratch (static device memory; no runtime allocation) ----
__device__ unsigned long long g_pack[MAXN];      // (cnt<<40) | fix24(sum_w)
__device__ __align__(16) float g_dinv[MAXN];
__device__ unsigned long long g_offcnt[MAXN];    // off | (cnt<<32)
__device__ int   g_rank[MAXE];                   // edge rank within dst segment
__device__ int   g_total;                        // global scan cursor
__device__ __align__(16) unsigned g_edge32[MAXE];            // src:17 | wq:15
__device__ __align__(16) uint2 g_xh[(size_t)MAXN * 32];      // dinv*x as fp16
__device__ __align__(16) uint2 g_agg16[(size_t)MAXN * 32];   // aggx as fp16
__device__ __align__(16) __half g_Mh[FDIM * NC];             // fused weights fp16
__device__ __align__(16) float g_bias[NC];                   // fused biases

__device__ __forceinline__ float tanhfast(float x) {
    float y;
    asm("tanh.approx.f32 %0, %1;" : "=f"(y) : "f"(x));
    return y;
}
__device__ __forceinline__ void ldmatrix_x4(unsigned& r0, unsigned& r1,
                                            unsigned& r2, unsigned& r3,
                                            unsigned addr) {
    asm volatile("ldmatrix.sync.aligned.m8n8.x4.shared.b16 {%0,%1,%2,%3}, [%4];"
                 : "=r"(r0), "=r"(r1), "=r"(r2), "=r"(r3) : "r"(addr));
}
__device__ __forceinline__ void ldmatrix_x2_trans(unsigned& r0, unsigned& r1,
                                                  unsigned addr) {
    asm volatile("ldmatrix.sync.aligned.m8n8.x2.trans.shared.b16 {%0,%1}, [%2];"
                 : "=r"(r0), "=r"(r1) : "r"(addr));
}
__device__ __forceinline__ void mma_f16(float* c, const unsigned* a,
                                        unsigned b0, unsigned b1) {
    asm volatile(
        "mma.sync.aligned.m16n8k16.row.col.f32.f16.f16.f32 "
        "{%0,%1,%2,%3},{%4,%5,%6,%7},{%8,%9},{%0,%1,%2,%3};"
        : "+f"(c[0]), "+f"(c[1]), "+f"(c[2]), "+f"(c[3])
        : "r"(a[0]), "r"(a[1]), "r"(a[2]), "r"(a[3]), "r"(b0), "r"(b1));
}
__device__ __forceinline__ float4 h4_to_f4(unsigned lo, unsigned hi) {
    float2 fa = __half22float2(*(__half2*)&lo);
    float2 fb = __half22float2(*(__half2*)&hi);
    return make_float4(fa.x, fa.y, fb.x, fb.y);
}

// ---------------- fused weights+bias + scratch zeroing (one launch) ---------
__global__ void __launch_bounds__(128) k_fuse(
        const float* __restrict__ Wcz, const float* __restrict__ Wch,
        const float* __restrict__ bcz, const float* __restrict__ bch,
        const float* __restrict__ Wlz, const float* __restrict__ Wlh,
        const float* __restrict__ blz, const float* __restrict__ blh, int n) {
    if (blockIdx.x >= NC) {
        int i = (blockIdx.x - NC) * 128 + threadIdx.x;
        if (i < n) g_pack[i] = 0ull;
        if (blockIdx.x == NC && threadIdx.x == 0) g_total = 0;
        return;
    }
    __shared__ float wl[HID];
    __shared__ float red[128];
    int j = blockIdx.x;                 // 0..199
    int t = threadIdx.x;                // 0..127
    int jj = (j < HID) ? j : j - HID;
    const float* A  = (j < HID) ? Wcz : Wch;
    const float* bc = (j < HID) ? bcz : bch;
    const float* Wl = (j < HID) ? Wlz : Wlh;
    const float* bl = (j < HID) ? blz : blh;

    float p = 0.0f;
    if (t < HID) {
        float v = Wl[t * HID + jj];
        wl[t] = v;
        p = bc[t] * v;
    }
    red[t] = p;
    __syncthreads();

    const float* Ar = A + t * HID;
    float s = 0.0f;
    #pragma unroll 4
    for (int k = 0; k < HID; k++)
        s = fmaf(Ar[k], wl[k], s);
    g_Mh[t * NC + j] = __float2half_rn(s);

    #pragma unroll
    for (int off = 64; off > 0; off >>= 1) {
        if (t < off) red[t] += red[t + off];
        __syncthreads();
    }
    if (t == 0) g_bias[j] = bl[jj] + red[0];
}

// ---------------- per-edge: packed atomic; prior count = edge rank (free) ---
__global__ void k_deg_acc(const int* __restrict__ ei,
                          const float* __restrict__ ew, int e) {
    int i = blockIdx.x * blockDim.x + threadIdx.x;
    if (i < e) {
        int d = ei[(size_t)e + i];
        unsigned long long fix =
            (unsigned long long)__float2uint_rn(ew[i] * FIXSCALE);
        unsigned long long prior = atomicAdd(&g_pack[d], (1ull << 40) | fix);
        g_rank[i] = (int)(prior >> 40);
    }
}

// ---------------- ONE-kernel scan: decode + local scan + atomic block base --
__global__ void k_scan(int n) {
    __shared__ int s[SCAN_BLK];
    __shared__ int base;
    int t = threadIdx.x;
    int idx = blockIdx.x * SCAN_BLK + t;
    int val = 0;
    if (idx < n) {
        unsigned long long p = g_pack[idx];
        val = (int)(p >> 40);
        float deg = 1.0f + (float)(p & FIXMASK) * (1.0f / FIXSCALE);
        g_dinv[idx] = rsqrtf(deg);
    }
    s[t] = val;
    __syncthreads();
    #pragma unroll
    for (int off = 1; off < SCAN_BLK; off <<= 1) {
        int v = (t >= off) ? s[t - off] : 0;
        __syncthreads();
        s[t] += v;
        __syncthreads();
    }
    if (t == SCAN_BLK - 1) base = atomicAdd(&g_total, s[t]);
    __syncthreads();
    if (idx < n) {
        int off = base + s[t] - val;        // exclusive
        g_offcnt[idx] = (unsigned long long)(unsigned)off |
                        ((unsigned long long)(unsigned)val << 32);
    }
}

// ---------------- merged: fill 32-bit CSR (no atomics) + prep xs=dinv*x -----
__global__ void k_fillprep(const int* __restrict__ ei,
                           const float* __restrict__ ew,
                           const float* __restrict__ x,
                           int e, int n, int fb) {
    if (blockIdx.x < fb) {
        int i = blockIdx.x * 256 + threadIdx.x;
        if (i >= e) return;
        int s = ei[i];
        int d = ei[(size_t)e + i];
        int pos = (int)(unsigned)g_offcnt[d] + g_rank[i];
        unsigned q = __float2uint_rn(ew[i] * WQ);
        if (q > 32767u) q = 32767u;
        g_edge32[pos] = (unsigned)s | (q << 17);
    } else {
        int i = (blockIdx.x - fb) * 256 + threadIdx.x;
        if (i >= n * 32) return;
        float dd = g_dinv[i >> 5];
        float4 v = ((const float4*)x)[i];
        uint2 u;
        *(__half2*)&u.x = __floats2half2_rn(v.x * dd, v.y * dd);
        *(__half2*)&u.y = __floats2half2_rn(v.z * dd, v.w * dd);
        g_xh[i] = u;
    }
}

// ---------------- gather: 2 nodes/warp, 32-bit edges, HFMA2 group-4 ---------
// agg[d] = dd * ( xs[d] + sum_e w_e * xs[src_e] ),  xs = dinv*x
__global__ void k_gather(int n) {
    int w = (blockIdx.x * blockDim.x + threadIdx.x) >> 5;
    int lane = threadIdx.x & 31;
    int sub = lane >> 4, sl = lane & 15;
    int node = w * 2 + sub;
    if (node >= n) return;
    unsigned long long oc = g_offcnt[node];
    int beg = (int)(unsigned)oc;
    int cnt = (int)(oc >> 32);
    float dd = g_dinv[node];

    const uint4* xh4 = (const uint4*)g_xh;        // 16 uint4 per node row
    uint4 u = xh4[(size_t)node * 16 + sl];
    float4 a0 = h4_to_f4(u.x, u.y);               // xs[d]
    float4 a1 = h4_to_f4(u.z, u.w);

    int j = beg, end = beg + cnt;
    int m4 = beg + (cnt & ~3);
    const __half2 z2 = __floats2half2_rn(0.0f, 0.0f);
    for (; j < m4; j += 4) {
        __half2 h0 = z2, h1 = z2, h2 = z2, h3 = z2;
        #pragma unroll
        for (int q = 0; q < 4; q++) {
            unsigned m = g_edge32[j + q];
            uint4 v = xh4[(size_t)(m & SRCMASK) * 16 + sl];
            __half2 wh =
                __float2half2_rn((float)(m >> 17) * (1.0f / WQ));
            h0 = __hfma2(*(__half2*)&v.x, wh, h0);
            h1 = __hfma2(*(__half2*)&v.y, wh, h1);
            h2 = __hfma2(*(__half2*)&v.z, wh, h2);
            h3 = __hfma2(*(__half2*)&v.w, wh, h3);
        }
        float2 f;
        f = __half22float2(h0); a0.x += f.x; a0.y += f.y;
        f = __half22float2(h1); a0.z += f.x; a0.w += f.y;
        f = __half22float2(h2); a1.x += f.x; a1.y += f.y;
        f = __half22float2(h3); a1.z += f.x; a1.w += f.y;
    }
    for (; j < end; j++) {
        unsigned m = g_edge32[j];
        float wq = (float)(m >> 17) * (1.0f / WQ);
        uint4 v = xh4[(size_t)(m & SRCMASK) * 16 + sl];
        float4 f = h4_to_f4(v.x, v.y);
        a0.x = fmaf(f.x, wq, a0.x); a0.y = fmaf(f.y, wq, a0.y);
        a0.z = fmaf(f.z, wq, a0.z); a0.w = fmaf(f.w, wq, a0.w);
        f = h4_to_f4(v.z, v.w);
        a1.x = fmaf(f.x, wq, a1.x); a1.y = fmaf(f.y, wq, a1.y);
        a1.z = fmaf(f.z, wq, a1.z); a1.w = fmaf(f.w, wq, a1.w);
    }
    uint4 o;
    *(__half2*)&o.x = __floats2half2_rn(a0.x * dd, a0.y * dd);
    *(__half2*)&o.y = __floats2half2_rn(a0.z * dd, a0.w * dd);
    *(__half2*)&o.z = __floats2half2_rn(a1.x * dd, a1.y * dd);
    *(__half2*)&o.w = __floats2half2_rn(a1.z * dd, a1.w * dd);
    ((uint4*)g_agg16)[(size_t)node * 16 + sl] = o;
}

// ---------------- fp16 tensor-core GEMM + fused TGCN epilogue ---------------
__global__ void __launch_bounds__(256, 1)
k_tgemm(const float* __restrict__ Wout, const float* __restrict__ bout,
        float* __restrict__ out, int n) {
    extern __shared__ __align__(16) char smem[];
    __half* As = (__half*)smem;                        // [128][AS_H]
    __half* Bs = (__half*)(smem + AS_BYTES);           // [FDIM][BS_H]

    __shared__ float sbias[NC];
    __shared__ float swout[HID];
    __shared__ float sbout;

    int tid = threadIdx.x;
    int n0 = blockIdx.x * 128;

    if (tid < NC)  sbias[tid] = g_bias[tid];
    if (tid < HID) swout[tid] = Wout[tid];
    if (tid == 0)  sbout = bout[0];

    for (int idx = tid; idx < 128 * 32; idx += 256) {
        int r = idx >> 5, c4 = idx & 31;
        int nn = n0 + r;
        uint2 u = (nn < n) ? g_agg16[(size_t)nn * 32 + c4] : make_uint2(0u, 0u);
        *(uint2*)&As[r * AS_H + c4 * 4] = u;
    }
    for (int idx = tid; idx < FDIM * 50; idx += 256) {
        int k = idx / 50, c = idx % 50;
        *(uint2*)&Bs[k * BS_H + c * 4] = ((const uint2*)g_Mh)[k * 50 + c];
    }
    __syncthreads();

    int lane = tid & 31, w = tid >> 5;
    int mw = w & 3, nw = w >> 2;
    int rbase = mw * 32;
    int nbase = nw * 96;
    int lr = lane >> 2, lc = lane & 3;

    unsigned as_base = (unsigned)__cvta_generic_to_shared(As);
    unsigned bs_base = (unsigned)__cvta_generic_to_shared(Bs);

    int a_idx = lane & 7, a_grp = lane >> 3;
    int b_row_lane = lane & 15;

    float c[2][13][4];
    #pragma unroll
    for (int ms = 0; ms < 2; ms++)
        #pragma unroll
        for (int t = 0; t < 13; t++)
            #pragma unroll
            for (int u = 0; u < 4; u++) c[ms][t][u] = 0.0f;

    #pragma unroll
    for (int ks = 0; ks < 8; ks++) {
        int k0 = ks * 16;
        unsigned a[2][4];
        #pragma unroll
        for (int ms = 0; ms < 2; ms++) {
            int row = rbase + ms * 16 + (a_grp & 1) * 8 + a_idx;
            int col = k0 + (a_grp >> 1) * 8;
            unsigned addr = as_base + (row * AS_H + col) * 2;
            ldmatrix_x4(a[ms][0], a[ms][1], a[ms][2], a[ms][3], addr);
        }
        #pragma unroll
        for (int t = 0; t < 13; t++) {
            int ncol = nbase + t * 8;
            unsigned baddr = bs_base + ((k0 + b_row_lane) * BS_H + ncol) * 2;
            unsigned b0, b1;
            ldmatrix_x2_trans(b0, b1, baddr);
            mma_f16(c[0][t], a[0], b0, b1);
            mma_f16(c[1][t], a[1], b0, b1);
        }
    }

    __syncthreads();
    float* Cs = (float*)smem;
    #pragma unroll
    for (int ms = 0; ms < 2; ms++) {
        #pragma unroll
        for (int t = 0; t < 13; t++) {
            int rr = rbase + ms * 16 + lr;
            int cc = nbase + t * 8 + lc * 2;
            *(float2*)&Cs[rr * CS_STRIDE + cc] =
                make_float2(c[ms][t][0], c[ms][t][1]);
            *(float2*)&Cs[(rr + 8) * CS_STRIDE + cc] =
                make_float2(c[ms][t][2], c[ms][t][3]);
        }
    }
    __syncthreads();

    int r = tid >> 1, half = tid & 1;
    int nn = n0 + r;
    const float* Cr = &Cs[r * CS_STRIDE];
    float sum = 0.0f;
    #pragma unroll 2
    for (int jj = 0; jj < 50; jj++) {
        int j = half * 50 + jj;
        float zr = Cr[j] + sbias[j];
        float hr = Cr[HID + j] + sbias[HID + j];
        float omz = 0.5f * (1.0f - tanhfast(0.5f * zr));   // 1 - sigmoid(zr)
        float v = fmaxf(omz * tanhfast(hr), 0.0f);
        sum = fmaf(v, swout[j], sum);
    }
    sum += __shfl_down_sync(0xffffffffu, sum, 1);
    if (half == 0 && nn < n) out[nn] = sum + sbout;
}

// ---------------- launch ----------------------------------------------------
extern "C" void kernel_launch(void* const* d_in, const int* in_sizes, int n_in,
                              void* d_out, int out_size) {
    const float* x    = (const float*)d_in[0];
    const int*   ei   = (const int*)d_in[1];     // int32 (JAX canonicalizes)
    const float* ew   = (const float*)d_in[2];
    const float* Wcz  = (const float*)d_in[3];
    const float* bcz  = (const float*)d_in[4];
    const float* Wch  = (const float*)d_in[7];
    const float* bch  = (const float*)d_in[8];
    const float* Wlz  = (const float*)d_in[9];
    const float* blz  = (const float*)d_in[10];
    const float* Wlh  = (const float*)d_in[13];
    const float* blh  = (const float*)d_in[14];
    const float* Wout = (const float*)d_in[15];
    const float* bout = (const float*)d_in[16];
    float*       out  = (float*)d_out;

    int n = in_sizes[0] / FDIM;    // 100000
    int e = in_sizes[2];           // 1600000
    int nb = (n + SCAN_BLK - 1) / SCAN_BLK;

    static bool attr_set = false;
    if (!attr_set) {
        cudaFuncSetAttribute(k_tgemm,
                             cudaFuncAttributeMaxDynamicSharedMemorySize,
                             SMEM_BYTES);
        attr_set = true;
    }

    k_fuse<<<NC + (n + 127) / 128, 128>>>(Wcz, Wch, bcz, bch,
                                          Wlz, Wlh, blz, blh, n);
    k_deg_acc<<<(e + 255) / 256, 256>>>(ei, ew, e);
    k_scan<<<nb, SCAN_BLK>>>(n);
    int fb = (e + 255) / 256;
    int pb = (n * 32 + 255) / 256;
    k_fillprep<<<fb + pb, 256>>>(ei, ew, x, e, n, fb);
    int gwarps = (n + 1) / 2;
    k_gather<<<(gwarps * 32 + 255) / 256, 256>>>(n);
    k_tgemm<<<(n + 127) / 128, 256, SMEM_BYTES>>>(Wout, bout, out, n);
}

// round 16
// speedup vs baseline: 1.1201x; 1.0397x over previous
#include <cuda_runtime.h>
#include <cuda_fp16.h>
#include <cstdint>
#include <math.h>

#define MAXN 100000
#define MAXE 1600000
#define FDIM 128
#define HID  100
#define NC   200                 // 2*HID fused output columns: [z | h]
#define SCAN_BLK 1024

// fp16 tensor-gemm smem geometry
#define AS_H 136                 // 272 B row ≡ 16 mod 128 -> conflict-free ldmatrix
#define BS_H 200                 // 400 B row ≡ 16 mod 128 -> conflict-free
#define CS_STRIDE 204            // f32 C stride
#define AS_BYTES (128 * AS_H * 2)          // 34,816
#define BS_BYTES (FDIM * BS_H * 2)         // 51,200
#define SMEM_BYTES (128 * CS_STRIDE * 4)   // 104,448  (C overlay dominates)

#define FIXSCALE 16777216.0f     // 2^24 fixed-point for edge-weight degree sums
#define FIXMASK ((1ull << 40) - 1)
#define WQ 32767.0f              // 15-bit edge-weight quantization
#define SRCMASK 0x1FFFFu         // 17 bits for src (N = 1e5 < 2^17)

// ---------------- scratch (static device memory; no runtime allocation) ----
__device__ unsigned long long g_pack[MAXN];      // (cnt<<40) | fix24(sum_w)
__device__ __align__(16) float g_dinv[MAXN];
__device__ unsigned long long g_offcnt[MAXN];    // off | (cnt<<32)
__device__ int   g_rank[MAXE];                   // edge rank within dst segment
__device__ int   g_total;                        // global scan cursor
__device__ __align__(16) unsigned g_edge32[MAXE];            // src:17 | wq:15
__device__ __align__(16) uint2 g_xh[(size_t)MAXN * 32];      // dinv*x as fp16
__device__ __align__(16) uint2 g_agg16[(size_t)MAXN * 32];   // aggx as fp16
__device__ __align__(16) __half g_Mh[FDIM * NC];             // fused weights fp16
__device__ __align__(16) float g_bias[NC];                   // fused biases

__device__ __forceinline__ float tanhfast(float x) {
    float y;
    asm("tanh.approx.f32 %0, %1;" : "=f"(y) : "f"(x));
    return y;
}
__device__ __forceinline__ void ldmatrix_x4(unsigned& r0, unsigned& r1,
                                            unsigned& r2, unsigned& r3,
                                            unsigned addr) {
    asm volatile("ldmatrix.sync.aligned.m8n8.x4.shared.b16 {%0,%1,%2,%3}, [%4];"
                 : "=r"(r0), "=r"(r1), "=r"(r2), "=r"(r3) : "r"(addr));
}
__device__ __forceinline__ void ldmatrix_x2_trans(unsigned& r0, unsigned& r1,
                                                  unsigned addr) {
    asm volatile("ldmatrix.sync.aligned.m8n8.x2.trans.shared.b16 {%0,%1}, [%2];"
                 : "=r"(r0), "=r"(r1) : "r"(addr));
}
__device__ __forceinline__ void mma_f16(float* c, const unsigned* a,
                                        unsigned b0, unsigned b1) {
    asm volatile(
        "mma.sync.aligned.m16n8k16.row.col.f32.f16.f16.f32 "
        "{%0,%1,%2,%3},{%4,%5,%6,%7},{%8,%9},{%0,%1,%2,%3};"
        : "+f"(c[0]), "+f"(c[1]), "+f"(c[2]), "+f"(c[3])
        : "r"(a[0]), "r"(a[1]), "r"(a[2]), "r"(a[3]), "r"(b0), "r"(b1));
}
__device__ __forceinline__ float4 h4_to_f4(unsigned lo, unsigned hi) {
    float2 fa = __half22float2(*(__half2*)&lo);
    float2 fb = __half22float2(*(__half2*)&hi);
    return make_float4(fa.x, fa.y, fb.x, fb.y);
}

// ---------------- fused weights+bias + scratch zeroing (one launch) ---------
__global__ void __launch_bounds__(128) k_fuse(
        const float* __restrict__ Wcz, const float* __restrict__ Wch,
        const float* __restrict__ bcz, const float* __restrict__ bch,
        const float* __restrict__ Wlz, const float* __restrict__ Wlh,
        const float* __restrict__ blz, const float* __restrict__ blh, int n) {
    if (blockIdx.x >= NC) {
        int i = (blockIdx.x - NC) * 128 + threadIdx.x;
        if (i < n) g_pack[i] = 0ull;
        if (blockIdx.x == NC && threadIdx.x == 0) g_total = 0;
        return;
    }
    __shared__ float wl[HID];
    __shared__ float red[128];
    int j = blockIdx.x;                 // 0..199
    int t = threadIdx.x;                // 0..127
    int jj = (j < HID) ? j : j - HID;
    const float* A  = (j < HID) ? Wcz : Wch;
    const float* bc = (j < HID) ? bcz : bch;
    const float* Wl = (j < HID) ? Wlz : Wlh;
    const float* bl = (j < HID) ? blz : blh;

    float p = 0.0f;
    if (t < HID) {
        float v = Wl[t * HID + jj];
        wl[t] = v;
        p = bc[t] * v;
    }
    red[t] = p;
    __syncthreads();

    const float* Ar = A + t * HID;
    float s = 0.0f;
    #pragma unroll 4
    for (int k = 0; k < HID; k++)
        s = fmaf(Ar[k], wl[k], s);
    g_Mh[t * NC + j] = __float2half_rn(s);

    #pragma unroll
    for (int off = 64; off > 0; off >>= 1) {
        if (t < off) red[t] += red[t + off];
        __syncthreads();
    }
    if (t == 0) g_bias[j] = bl[jj] + red[0];
}

// ---------------- per-edge: packed atomic; prior count = edge rank (free) ---
__global__ void k_deg_acc(const int* __restrict__ ei,
                          const float* __restrict__ ew, int e) {
    int i = blockIdx.x * blockDim.x + threadIdx.x;
    if (i < e) {
        int d = ei[(size_t)e + i];
        unsigned long long fix =
            (unsigned long long)__float2uint_rn(ew[i] * FIXSCALE);
        unsigned long long prior = atomicAdd(&g_pack[d], (1ull << 40) | fix);
        g_rank[i] = (int)(prior >> 40);
    }
}

// ---------------- ONE-kernel scan: decode + local scan + atomic block base --
__global__ void k_scan(int n) {
    __shared__ int s[SCAN_BLK];
    __shared__ int base;
    int t = threadIdx.x;
    int idx = blockIdx.x * SCAN_BLK + t;
    int val = 0;
    if (idx < n) {
        unsigned long long p = g_pack[idx];
        val = (int)(p >> 40);
        float deg = 1.0f + (float)(p & FIXMASK) * (1.0f / FIXSCALE);
        g_dinv[idx] = rsqrtf(deg);
    }
    s[t] = val;
    __syncthreads();
    #pragma unroll
    for (int off = 1; off < SCAN_BLK; off <<= 1) {
        int v = (t >= off) ? s[t - off] : 0;
        __syncthreads();
        s[t] += v;
        __syncthreads();
    }
    if (t == SCAN_BLK - 1) base = atomicAdd(&g_total, s[t]);
    __syncthreads();
    if (idx < n) {
        int off = base + s[t] - val;        // exclusive
        g_offcnt[idx] = (unsigned long long)(unsigned)off |
                        ((unsigned long long)(unsigned)val << 32);
    }
}

// ---------------- merged: fill 32-bit CSR (no atomics) + prep xs=dinv*x -----
__global__ void k_fillprep(const int* __restrict__ ei,
                           const float* __restrict__ ew,
                           const float* __restrict__ x,
                           int e, int n, int fb) {
    if (blockIdx.x < fb) {
        int i = blockIdx.x * 256 + threadIdx.x;
        if (i >= e) return;
        int s = ei[i];
        int d = ei[(size_t)e + i];
        int pos = (int)(unsigned)g_offcnt[d] + g_rank[i];
        unsigned q = __float2uint_rn(ew[i] * WQ);
        if (q > 32767u) q = 32767u;
        g_edge32[pos] = (unsigned)s | (q << 17);
    } else {
        int i = (blockIdx.x - fb) * 256 + threadIdx.x;
        if (i >= n * 32) return;
        float dd = g_dinv[i >> 5];
        float4 v = ((const float4*)x)[i];
        uint2 u;
        *(__half2*)&u.x = __floats2half2_rn(v.x * dd, v.y * dd);
        *(__half2*)&u.y = __floats2half2_rn(v.z * dd, v.w * dd);
        g_xh[i] = u;
    }
}

// ---------------- gather: 2 nodes/warp, 32-bit edges, HFMA2 group-4 ---------
__global__ void k_gather(int n) {
    int w = (blockIdx.x * blockDim.x + threadIdx.x) >> 5;
    int lane = threadIdx.x & 31;
    int sub = lane >> 4, sl = lane & 15;
    int node = w * 2 + sub;
    if (node >= n) return;
    unsigned long long oc = g_offcnt[node];
    int beg = (int)(unsigned)oc;
    int cnt = (int)(oc >> 32);
    float dd = g_dinv[node];

    const uint4* xh4 = (const uint4*)g_xh;        // 16 uint4 per node row
    uint4 u = xh4[(size_t)node * 16 + sl];
    float4 a0 = h4_to_f4(u.x, u.y);               // xs[d]
    float4 a1 = h4_to_f4(u.z, u.w);

    int j = beg, end = beg + cnt;
    int m4 = beg + (cnt & ~3);
    const __half2 z2 = __floats2half2_rn(0.0f, 0.0f);
    for (; j < m4; j += 4) {
        __half2 h0 = z2, h1 = z2, h2 = z2, h3 = z2;
        #pragma unroll
        for (int q = 0; q < 4; q++) {
            unsigned m = g_edge32[j + q];
            uint4 v = xh4[(size_t)(m & SRCMASK) * 16 + sl];
            __half2 wh =
                __float2half2_rn((float)(m >> 17) * (1.0f / WQ));
            h0 = __hfma2(*(__half2*)&v.x, wh, h0);
            h1 = __hfma2(*(__half2*)&v.y, wh, h1);
            h2 = __hfma2(*(__half2*)&v.z, wh, h2);
            h3 = __hfma2(*(__half2*)&v.w, wh, h3);
        }
        float2 f;
        f = __half22float2(h0); a0.x += f.x; a0.y += f.y;
        f = __half22float2(h1); a0.z += f.x; a0.w += f.y;
        f = __half22float2(h2); a1.x += f.x; a1.y += f.y;
        f = __half22float2(h3); a1.z += f.x; a1.w += f.y;
    }
    for (; j < end; j++) {
        unsigned m = g_edge32[j];
        float wq = (float)(m >> 17) * (1.0f / WQ);
        uint4 v = xh4[(size_t)(m & SRCMASK) * 16 + sl];
        float4 f = h4_to_f4(v.x, v.y);
        a0.x = fmaf(f.x, wq, a0.x); a0.y = fmaf(f.y, wq, a0.y);
        a0.z = fmaf(f.z, wq, a0.z); a0.w = fmaf(f.w, wq, a0.w);
        f = h4_to_f4(v.z, v.w);
        a1.x = fmaf(f.x, wq, a1.x); a1.y = fmaf(f.y, wq, a1.y);
        a1.z = fmaf(f.z, wq, a1.z); a1.w = fmaf(f.w, wq, a1.w);
    }
    uint4 o;
    *(__half2*)&o.x = __floats2half2_rn(a0.x * dd, a0.y * dd);
    *(__half2*)&o.y = __floats2half2_rn(a0.z * dd, a0.w * dd);
    *(__half2*)&o.z = __floats2half2_rn(a1.x * dd, a1.y * dd);
    *(__half2*)&o.w = __floats2half2_rn(a1.z * dd, a1.w * dd);
    ((uint4*)g_agg16)[(size_t)node * 16 + sl] = o;
}

// ---------------- fp16 tensor-core GEMM + fused TGCN epilogue ---------------
// 512 threads = 16 warps: 4 m-warps x 4 n-warps on a 128x200 tile, K=128.
// Each warp: 32 rows (2x16) x 7 n-tiles (nbase = nw*48, tiles overlap benignly).
__global__ void __launch_bounds__(512, 1)
k_tgemm(const float* __restrict__ Wout, const float* __restrict__ bout,
        float* __restrict__ out, int n) {
    extern __shared__ __align__(16) char smem[];
    __half* As = (__half*)smem;                        // [128][AS_H]
    __half* Bs = (__half*)(smem + AS_BYTES);           // [FDIM][BS_H]

    __shared__ float sbias[NC];
    __shared__ float swout[HID];
    __shared__ float sbout;

    int tid = threadIdx.x;
    int n0 = blockIdx.x * 128;

    if (tid < NC)  sbias[tid] = g_bias[tid];
    if (tid < HID) swout[tid] = Wout[tid];
    if (tid == 0)  sbout = bout[0];

    for (int idx = tid; idx < 128 * 32; idx += 512) {
        int r = idx >> 5, c4 = idx & 31;
        int nn = n0 + r;
        uint2 u = (nn < n) ? g_agg16[(size_t)nn * 32 + c4] : make_uint2(0u, 0u);
        *(uint2*)&As[r * AS_H + c4 * 4] = u;
    }
    for (int idx = tid; idx < FDIM * 50; idx += 512) {
        int k = idx / 50, c = idx % 50;
        *(uint2*)&Bs[k * BS_H + c * 4] = ((const uint2*)g_Mh)[k * 50 + c];
    }
    __syncthreads();

    int lane = tid & 31, w = tid >> 5;
    int mw = w & 3, nw = w >> 2;          // 4 x 4 warp grid
    int rbase = mw * 32;
    int nbase = nw * 48;                  // 4 warps x 7 tiles x 8 = covers 200
    int lr = lane >> 2, lc = lane & 3;

    unsigned as_base = (unsigned)__cvta_generic_to_shared(As);
    unsigned bs_base = (unsigned)__cvta_generic_to_shared(Bs);

    int a_idx = lane & 7, a_grp = lane >> 3;
    int b_row_lane = lane & 15;

    float c[2][7][4];
    #pragma unroll
    for (int ms = 0; ms < 2; ms++)
        #pragma unroll
        for (int t = 0; t < 7; t++)
            #pragma unroll
            for (int u = 0; u < 4; u++) c[ms][t][u] = 0.0f;

    #pragma unroll
    for (int ks = 0; ks < 8; ks++) {
        int k0 = ks * 16;
        unsigned a[2][4];
        #pragma unroll
        for (int ms = 0; ms < 2; ms++) {
            int row = rbase + ms * 16 + (a_grp & 1) * 8 + a_idx;
            int col = k0 + (a_grp >> 1) * 8;
            unsigned addr = as_base + (row * AS_H + col) * 2;
            ldmatrix_x4(a[ms][0], a[ms][1], a[ms][2], a[ms][3], addr);
        }
        #pragma unroll
        for (int t = 0; t < 7; t++) {
            int ncol = nbase + t * 8;
            unsigned baddr = bs_base + ((k0 + b_row_lane) * BS_H + ncol) * 2;
            unsigned b0, b1;
            ldmatrix_x2_trans(b0, b1, baddr);
            mma_f16(c[0][t], a[0], b0, b1);
            mma_f16(c[1][t], a[1], b0, b1);
        }
    }

    __syncthreads();
    float* Cs = (float*)smem;
    #pragma unroll
    for (int ms = 0; ms < 2; ms++) {
        #pragma unroll
        for (int t = 0; t < 7; t++) {
            int rr = rbase + ms * 16 + lr;
            int cc = nbase + t * 8 + lc * 2;
            *(float2*)&Cs[rr * CS_STRIDE + cc] =
                make_float2(c[ms][t][0], c[ms][t][1]);
            *(float2*)&Cs[(rr + 8) * CS_STRIDE + cc] =
                make_float2(c[ms][t][2], c[ms][t][3]);
        }
    }
    __syncthreads();

    // epilogue: 4 threads per row, 25 cols each
    int r = tid >> 2, quad = tid & 3;
    int nn = n0 + r;
    const float* Cr = &Cs[r * CS_STRIDE];
    float sum = 0.0f;
    #pragma unroll 5
    for (int jj = 0; jj < 25; jj++) {
        int j = quad * 25 + jj;
        float zr = Cr[j] + sbias[j];
        float hr = Cr[HID + j] + sbias[HID + j];
        float omz = 0.5f * (1.0f - tanhfast(0.5f * zr));   // 1 - sigmoid(zr)
        float v = fmaxf(omz * tanhfast(hr), 0.0f);
        sum = fmaf(v, swout[j], sum);
    }
    sum += __shfl_down_sync(0xffffffffu, sum, 1);
    sum += __shfl_down_sync(0xffffffffu, sum, 2);
    if (quad == 0 && nn < n) out[nn] = sum + sbout;
}

// ---------------- launch ----------------------------------------------------
extern "C" void kernel_launch(void* const* d_in, const int* in_sizes, int n_in,
                              void* d_out, int out_size) {
    const float* x    = (const float*)d_in[0];
    const int*   ei   = (const int*)d_in[1];     // int32 (JAX canonicalizes)
    const float* ew   = (const float*)d_in[2];
    const float* Wcz  = (const float*)d_in[3];
    const float* bcz  = (const float*)d_in[4];
    const float* Wch  = (const float*)d_in[7];
    const float* bch  = (const float*)d_in[8];
    const float* Wlz  = (const float*)d_in[9];
    const float* blz  = (const float*)d_in[10];
    const float* Wlh  = (const float*)d_in[13];
    const float* blh  = (const float*)d_in[14];
    const float* Wout = (const float*)d_in[15];
    const float* bout = (const float*)d_in[16];
    float*       out  = (float*)d_out;

    int n = in_sizes[0] / FDIM;    // 100000
    int e = in_sizes[2];           // 1600000
    int nb = (n + SCAN_BLK - 1) / SCAN_BLK;

    static bool attr_set = false;
    if (!attr_set) {
        cudaFuncSetAttribute(k_tgemm,
                             cudaFuncAttributeMaxDynamicSharedMemorySize,
                             SMEM_BYTES);
        attr_set = true;
    }

    k_fuse<<<NC + (n + 127) / 128, 128>>>(Wcz, Wch, bcz, bch,
                                          Wlz, Wlh, blz, blh, n);
    k_deg_acc<<<(e + 255) / 256, 256>>>(ei, ew, e);
    k_scan<<<nb, SCAN_BLK>>>(n);
    int fb = (e + 255) / 256;
    int pb = (n * 32 + 255) / 256;
    k_fillprep<<<fb + pb, 256>>>(ei, ew, x, e, n, fb);
    int gwarps = (n + 1) / 2;
    k_gather<<<(gwarps * 32 + 255) / 256, 256>>>(n);
    k_tgemm<<<(n + 127) / 128, 512, SMEM_BYTES>>>(Wout, bout, out, n);
}

// round 17
// speedup vs baseline: 1.1998x; 1.0711x over previous
#include <cuda_runtime.h>
#include <cuda_fp16.h>
#include <cstdint>
#include <math.h>

#define MAXN 100000
#define MAXE 1600000
#define FDIM 128
#define HID  100
#define NC   200                 // 2*HID fused output columns: [z | h]
#define SCAN_BLK 1024

// fp16 tensor-gemm smem geometry
#define AS_H 136                 // 272 B row ≡ 16 mod 128 -> conflict-free ldmatrix
#define BS_H 200                 // 400 B row ≡ 16 mod 128 -> conflict-free
#define CS_STRIDE 204            // f32 C stride
#define AS_BYTES (128 * AS_H * 2)          // 34,816
#define BS_BYTES (FDIM * BS_H * 2)         // 51,200
#define SMEM_BYTES (128 * CS_STRIDE * 4)   // 104,448  (C overlay dominates)

#define FIXSCALE 16777216.0f     // 2^24 fixed-point for edge-weight degree sums
#define FIXMASK ((1ull << 40) - 1)
#define WQ 32767.0f              // 15-bit edge-weight quantization
#define SRCMASK 0x1FFFFu         // 17 bits for src (N = 1e5 < 2^17)

// ---------------- scratch (static device memory; no runtime allocation) ----
// INVARIANT: g_pack and g_total are zero at kernel_launch entry (zero-init at
// module load; re-zeroed by k_fillprep at the end of every call -> graph-safe).
__device__ unsigned long long g_pack[MAXN];      // (cnt<<40) | fix24(sum_w)
__device__ __align__(16) float g_dinv[MAXN];
__device__ unsigned long long g_offcnt[MAXN];    // off | (cnt<<32)
__device__ int   g_rank[MAXE];                   // edge rank within dst segment
__device__ int   g_total;                        // global scan cursor
__device__ __align__(16) unsigned g_edge32[MAXE];            // src:17 | wq:15
__device__ __align__(16) uint2 g_xh[(size_t)MAXN * 32];      // dinv*x as fp16
__device__ __align__(16) uint2 g_agg16[(size_t)MAXN * 32];   // aggx as fp16
__device__ __align__(16) __half g_Mh[FDIM * NC];             // fused weights fp16
__device__ __align__(16) float g_bias[NC];                   // fused biases

__device__ __forceinline__ float tanhfast(float x) {
    float y;
    asm("tanh.approx.f32 %0, %1;" : "=f"(y) : "f"(x));
    return y;
}
__device__ __forceinline__ void ldmatrix_x4(unsigned& r0, unsigned& r1,
                                            unsigned& r2, unsigned& r3,
                                            unsigned addr) {
    asm volatile("ldmatrix.sync.aligned.m8n8.x4.shared.b16 {%0,%1,%2,%3}, [%4];"
                 : "=r"(r0), "=r"(r1), "=r"(r2), "=r"(r3) : "r"(addr));
}
__device__ __forceinline__ void ldmatrix_x2_trans(unsigned& r0, unsigned& r1,
                                                  unsigned addr) {
    asm volatile("ldmatrix.sync.aligned.m8n8.x2.trans.shared.b16 {%0,%1}, [%2];"
                 : "=r"(r0), "=r"(r1) : "r"(addr));
}
__device__ __forceinline__ void mma_f16(float* c, const unsigned* a,
                                        unsigned b0, unsigned b1) {
    asm volatile(
        "mma.sync.aligned.m16n8k16.row.col.f32.f16.f16.f32 "
        "{%0,%1,%2,%3},{%4,%5,%6,%7},{%8,%9},{%0,%1,%2,%3};"
        : "+f"(c[0]), "+f"(c[1]), "+f"(c[2]), "+f"(c[3])
        : "r"(a[0]), "r"(a[1]), "r"(a[2]), "r"(a[3]), "r"(b0), "r"(b1));
}
__device__ __forceinline__ float4 h4_to_f4(unsigned lo, unsigned hi) {
    float2 fa = __half22float2(*(__half2*)&lo);
    float2 fb = __half22float2(*(__half2*)&hi);
    return make_float4(fa.x, fa.y, fb.x, fb.y);
}

// ---------------- merged: fused weights+bias  +  per-edge degree atomics ----
// blocks [0, NC): fuse M/bias; blocks [NC, ...): deg_acc (g_pack pre-zeroed).
__global__ void __launch_bounds__(128) k_fuse_deg(
        const float* __restrict__ Wcz, const float* __restrict__ Wch,
        const float* __restrict__ bcz, const float* __restrict__ bch,
        const float* __restrict__ Wlz, const float* __restrict__ Wlh,
        const float* __restrict__ blz, const float* __restrict__ blh,
        const int* __restrict__ ei, const float* __restrict__ ew, int e) {
    if (blockIdx.x >= NC) {
        int i = (blockIdx.x - NC) * 128 + threadIdx.x;
        if (i < e) {
            int d = ei[(size_t)e + i];
            unsigned long long fix =
                (unsigned long long)__float2uint_rn(ew[i] * FIXSCALE);
            unsigned long long prior =
                atomicAdd(&g_pack[d], (1ull << 40) | fix);
            g_rank[i] = (int)(prior >> 40);
        }
        return;
    }
    __shared__ float wl[HID];
    __shared__ float red[128];
    int j = blockIdx.x;                 // 0..199
    int t = threadIdx.x;                // 0..127
    int jj = (j < HID) ? j : j - HID;
    const float* A  = (j < HID) ? Wcz : Wch;
    const float* bc = (j < HID) ? bcz : bch;
    const float* Wl = (j < HID) ? Wlz : Wlh;
    const float* bl = (j < HID) ? blz : blh;

    float p = 0.0f;
    if (t < HID) {
        float v = Wl[t * HID + jj];
        wl[t] = v;
        p = bc[t] * v;
    }
    red[t] = p;
    __syncthreads();

    const float* Ar = A + t * HID;
    float s = 0.0f;
    #pragma unroll 4
    for (int k = 0; k < HID; k++)
        s = fmaf(Ar[k], wl[k], s);
    g_Mh[t * NC + j] = __float2half_rn(s);

    #pragma unroll
    for (int off = 64; off > 0; off >>= 1) {
        if (t < off) red[t] += red[t + off];
        __syncthreads();
    }
    if (t == 0) g_bias[j] = bl[jj] + red[0];
}

// ---------------- ONE-kernel scan: decode + local scan + atomic block base --
__global__ void k_scan(int n) {
    __shared__ int s[SCAN_BLK];
    __shared__ int base;
    int t = threadIdx.x;
    int idx = blockIdx.x * SCAN_BLK + t;
    int val = 0;
    if (idx < n) {
        unsigned long long p = g_pack[idx];
        val = (int)(p >> 40);
        float deg = 1.0f + (float)(p & FIXMASK) * (1.0f / FIXSCALE);
        g_dinv[idx] = rsqrtf(deg);
    }
    s[t] = val;
    __syncthreads();
    #pragma unroll
    for (int off = 1; off < SCAN_BLK; off <<= 1) {
        int v = (t >= off) ? s[t - off] : 0;
        __syncthreads();
        s[t] += v;
        __syncthreads();
    }
    if (t == SCAN_BLK - 1) base = atomicAdd(&g_total, s[t]);
    __syncthreads();
    if (idx < n) {
        int off = base + s[t] - val;        // exclusive
        g_offcnt[idx] = (unsigned long long)(unsigned)off |
                        ((unsigned long long)(unsigned)val << 32);
    }
}

// ---------------- merged: fill 32-bit CSR + prep xs=dinv*x + reset scratch --
__global__ void k_fillprep(const int* __restrict__ ei,
                           const float* __restrict__ ew,
                           const float* __restrict__ x,
                           int e, int n, int fb) {
    if (blockIdx.x < fb) {
        int i = blockIdx.x * 256 + threadIdx.x;
        if (i >= e) return;
        int s = ei[i];
        int d = ei[(size_t)e + i];
        int pos = (int)(unsigned)g_offcnt[d] + g_rank[i];
        unsigned q = __float2uint_rn(ew[i] * WQ);
        if (q > 32767u) q = 32767u;
        g_edge32[pos] = (unsigned)s | (q << 17);
    } else {
        int i = (blockIdx.x - fb) * 256 + threadIdx.x;
        if (i < n) g_pack[i] = 0ull;          // reset for next graph replay
        if (blockIdx.x == fb && threadIdx.x == 0) g_total = 0;
        if (i >= n * 32) return;
        float dd = g_dinv[i >> 5];
        float4 v = ((const float4*)x)[i];
        uint2 u;
        *(__half2*)&u.x = __floats2half2_rn(v.x * dd, v.y * dd);
        *(__half2*)&u.y = __floats2half2_rn(v.z * dd, v.w * dd);
        g_xh[i] = u;
    }
}

// ---------------- gather: 2 nodes/warp, 32-bit edges, HFMA2 group-4 ---------
__global__ void k_gather(int n) {
    int w = (blockIdx.x * blockDim.x + threadIdx.x) >> 5;
    int lane = threadIdx.x & 31;
    int sub = lane >> 4, sl = lane & 15;
    int node = w * 2 + sub;
    if (node >= n) return;
    unsigned long long oc = g_offcnt[node];
    int beg = (int)(unsigned)oc;
    int cnt = (int)(oc >> 32);
    float dd = g_dinv[node];

    const uint4* xh4 = (const uint4*)g_xh;        // 16 uint4 per node row
    uint4 u = xh4[(size_t)node * 16 + sl];
    float4 a0 = h4_to_f4(u.x, u.y);               // xs[d]
    float4 a1 = h4_to_f4(u.z, u.w);

    int j = beg, end = beg + cnt;
    int m4 = beg + (cnt & ~3);
    const __half2 z2 = __floats2half2_rn(0.0f, 0.0f);
    for (; j < m4; j += 4) {
        __half2 h0 = z2, h1 = z2, h2 = z2, h3 = z2;
        #pragma unroll
        for (int q = 0; q < 4; q++) {
            unsigned m = g_edge32[j + q];
            uint4 v = xh4[(size_t)(m & SRCMASK) * 16 + sl];
            __half2 wh =
                __float2half2_rn((float)(m >> 17) * (1.0f / WQ));
            h0 = __hfma2(*(__half2*)&v.x, wh, h0);
            h1 = __hfma2(*(__half2*)&v.y, wh, h1);
            h2 = __hfma2(*(__half2*)&v.z, wh, h2);
            h3 = __hfma2(*(__half2*)&v.w, wh, h3);
        }
        float2 f;
        f = __half22float2(h0); a0.x += f.x; a0.y += f.y;
        f = __half22float2(h1); a0.z += f.x; a0.w += f.y;
        f = __half22float2(h2); a1.x += f.x; a1.y += f.y;
        f = __half22float2(h3); a1.z += f.x; a1.w += f.y;
    }
    for (; j < end; j++) {
        unsigned m = g_edge32[j];
        float wq = (float)(m >> 17) * (1.0f / WQ);
        uint4 v = xh4[(size_t)(m & SRCMASK) * 16 + sl];
        float4 f = h4_to_f4(v.x, v.y);
        a0.x = fmaf(f.x, wq, a0.x); a0.y = fmaf(f.y, wq, a0.y);
        a0.z = fmaf(f.z, wq, a0.z); a0.w = fmaf(f.w, wq, a0.w);
        f = h4_to_f4(v.z, v.w);
        a1.x = fmaf(f.x, wq, a1.x); a1.y = fmaf(f.y, wq, a1.y);
        a1.z = fmaf(f.z, wq, a1.z); a1.w = fmaf(f.w, wq, a1.w);
    }
    uint4 o;
    *(__half2*)&o.x = __floats2half2_rn(a0.x * dd, a0.y * dd);
    *(__half2*)&o.y = __floats2half2_rn(a0.z * dd, a0.w * dd);
    *(__half2*)&o.z = __floats2half2_rn(a1.x * dd, a1.y * dd);
    *(__half2*)&o.w = __floats2half2_rn(a1.z * dd, a1.w * dd);
    ((uint4*)g_agg16)[(size_t)node * 16 + sl] = o;
}

// ---------------- fp16 tensor-core GEMM + fused TGCN epilogue ---------------
// 512 threads = 16 warps: 4 m-warps x 4 n-warps on a 128x200 tile, K=128.
__global__ void __launch_bounds__(512, 1)
k_tgemm(const float* __restrict__ Wout, const float* __restrict__ bout,
        float* __restrict__ out, int n) {
    extern __shared__ __align__(16) char smem[];
    __half* As = (__half*)smem;                        // [128][AS_H]
    __half* Bs = (__half*)(smem + AS_BYTES);           // [FDIM][BS_H]

    __shared__ float sbias[NC];
    __shared__ float swout[HID];
    __shared__ float sbout;

    int tid = threadIdx.x;
    int n0 = blockIdx.x * 128;

    if (tid < NC)  sbias[tid] = g_bias[tid];
    if (tid < HID) swout[tid] = Wout[tid];
    if (tid == 0)  sbout = bout[0];

    for (int idx = tid; idx < 128 * 32; idx += 512) {
        int r = idx >> 5, c4 = idx & 31;
        int nn = n0 + r;
        uint2 u = (nn < n) ? g_agg16[(size_t)nn * 32 + c4] : make_uint2(0u, 0u);
        *(uint2*)&As[r * AS_H + c4 * 4] = u;
    }
    for (int idx = tid; idx < FDIM * 50; idx += 512) {
        int k = idx / 50, c = idx % 50;
        *(uint2*)&Bs[k * BS_H + c * 4] = ((const uint2*)g_Mh)[k * 50 + c];
    }
    __syncthreads();

    int lane = tid & 31, w = tid >> 5;
    int mw = w & 3, nw = w >> 2;          // 4 x 4 warp grid
    int rbase = mw * 32;
    int nbase = nw * 48;                  // 4 warps x 7 tiles x 8 covers 200
    int lr = lane >> 2, lc = lane & 3;

    unsigned as_base = (unsigned)__cvta_generic_to_shared(As);
    unsigned bs_base = (unsigned)__cvta_generic_to_shared(Bs);

    int a_idx = lane & 7, a_grp = lane >> 3;
    int b_row_lane = lane & 15;

    float c[2][7][4];
    #pragma unroll
    for (int ms = 0; ms < 2; ms++)
        #pragma unroll
        for (int t = 0; t < 7; t++)
            #pragma unroll
            for (int u = 0; u < 4; u++) c[ms][t][u] = 0.0f;

    #pragma unroll
    for (int ks = 0; ks < 8; ks++) {
        int k0 = ks * 16;
        unsigned a[2][4];
        #pragma unroll
        for (int ms = 0; ms < 2; ms++) {
            int row = rbase + ms * 16 + (a_grp & 1) * 8 + a_idx;
            int col = k0 + (a_grp >> 1) * 8;
            unsigned addr = as_base + (row * AS_H + col) * 2;
            ldmatrix_x4(a[ms][0], a[ms][1], a[ms][2], a[ms][3], addr);
        }
        #pragma unroll
        for (int t = 0; t < 7; t++) {
            int ncol = nbase + t * 8;
            unsigned baddr = bs_base + ((k0 + b_row_lane) * BS_H + ncol) * 2;
            unsigned b0, b1;
            ldmatrix_x2_trans(b0, b1, baddr);
            mma_f16(c[0][t], a[0], b0, b1);
            mma_f16(c[1][t], a[1], b0, b1);
        }
    }

    __syncthreads();
    float* Cs = (float*)smem;
    #pragma unroll
    for (int ms = 0; ms < 2; ms++) {
        #pragma unroll
        for (int t = 0; t < 7; t++) {
            int rr = rbase + ms * 16 + lr;
            int cc = nbase + t * 8 + lc * 2;
            *(float2*)&Cs[rr * CS_STRIDE + cc] =
                make_float2(c[ms][t][0], c[ms][t][1]);
            *(float2*)&Cs[(rr + 8) * CS_STRIDE + cc] =
                make_float2(c[ms][t][2], c[ms][t][3]);
        }
    }
    __syncthreads();

    // epilogue: 4 threads per row, 25 cols each
    int r = tid >> 2, quad = tid & 3;
    int nn = n0 + r;
    const float* Cr = &Cs[r * CS_STRIDE];
    float sum = 0.0f;
    #pragma unroll 5
    for (int jj = 0; jj < 25; jj++) {
        int j = quad * 25 + jj;
        float zr = Cr[j] + sbias[j];
        float hr = Cr[HID + j] + sbias[HID + j];
        float omz = 0.5f * (1.0f - tanhfast(0.5f * zr));   // 1 - sigmoid(zr)
        float v = fmaxf(omz * tanhfast(hr), 0.0f);
        sum = fmaf(v, swout[j], sum);
    }
    sum += __shfl_down_sync(0xffffffffu, sum, 1);
    sum += __shfl_down_sync(0xffffffffu, sum, 2);
    if (quad == 0 && nn < n) out[nn] = sum + sbout;
}

// ---------------- launch ----------------------------------------------------
extern "C" void kernel_launch(void* const* d_in, const int* in_sizes, int n_in,
                              void* d_out, int out_size) {
    const float* x    = (const float*)d_in[0];
    const int*   ei   = (const int*)d_in[1];     // int32 (JAX canonicalizes)
    const float* ew   = (const float*)d_in[2];
    const float* Wcz  = (const float*)d_in[3];
    const float* bcz  = (const float*)d_in[4];
    const float* Wch  = (const float*)d_in[7];
    const float* bch  = (const float*)d_in[8];
    const float* Wlz  = (const float*)d_in[9];
    const float* blz  = (const float*)d_in[10];
    const float* Wlh  = (const float*)d_in[13];
    const float* blh  = (const float*)d_in[14];
    const float* Wout = (const float*)d_in[15];
    const float* bout = (const float*)d_in[16];
    float*       out  = (float*)d_out;

    int n = in_sizes[0] / FDIM;    // 100000
    int e = in_sizes[2];           // 1600000
    int nb = (n + SCAN_BLK - 1) / SCAN_BLK;

    static bool attr_set = false;
    if (!attr_set) {
        cudaFuncSetAttribute(k_tgemm,
                             cudaFuncAttributeMaxDynamicSharedMemorySize,
                             SMEM_BYTES);
        attr_set = true;
    }

    k_fuse_deg<<<NC + (e + 127) / 128, 128>>>(Wcz, Wch, bcz, bch,
                                              Wlz, Wlh, blz, blh, ei, ew, e);
    k_scan<<<nb, SCAN_BLK>>>(n);
    int fb = (e + 255) / 256;
    int pb = (n * 32 + 255) / 256;
    k_fillprep<<<fb + pb, 256>>>(ei, ew, x, e, n, fb);
    int gwarps = (n + 1) / 2;
    k_gather<<<(gwarps * 32 + 255) / 256, 256>>>(n);
    k_tgemm<<<(n + 127) / 128, 512, SMEM_BYTES>>>(Wout, bout, out, n);
}